// round 14
// baseline (speedup 1.0000x reference)
#include <cuda_runtime.h>
#include <cuda_fp16.h>
#include <cstdint>

#define BATCH 512
#define NTOK  256
#define MTOT  (BATCH*NTOK)

__device__ __half g_w[294912];
__device__ __half g_X [(size_t)MTOT*512];
__device__ __half g_G [(size_t)MTOT*256];
__device__ __half g_Cv[(size_t)MTOT*256];
__device__ int    g_slot[MTOT];
__device__ int    g_cnt;

__constant__ int WOFF[9] = {0,65536,98304,131072,163840,196608,229376,262144,294912};

__global__ void convert_w(const float* w0,const float* w1,const float* w2,const float* w3,
                          const float* w4,const float* w5,const float* w6,const float* w7)
{
    int i = blockIdx.x*blockDim.x + threadIdx.x;
    if (i == 0) g_cnt = 0;
    if (i >= 294912) return;
    const float* p[8] = {w0,w1,w2,w3,w4,w5,w6,w7};
    int s = 0;
    while (i >= WOFF[s+1]) s++;
    g_w[i] = __float2half_rn(p[s][i - WOFF[s]]);
}

__global__ void __launch_bounds__(1024) stage1(const float* __restrict__ h0,
                                               const float* __restrict__ hT)
{
    __shared__ int flg[32], pre[32];
    int warp = threadIdx.x >> 5, lane = threadIdx.x & 31;
    int tok = blockIdx.x*32 + warp;
    const float4* p0 = (const float4*)(h0 + (size_t)tok*256);
    const float4* p1 = (const float4*)(hT + (size_t)tok*256);
    float4 a0 = p0[lane], a1 = p0[lane+32];
    float4 b0 = p1[lane], b1 = p1[lane+32];
    float s = a0.x+a0.y+a0.z+a0.w + a1.x+a1.y+a1.z+a1.w;
    #pragma unroll
    for (int o = 16; o > 0; o >>= 1) s += __shfl_xor_sync(0xffffffffu, s, o);
    int act = (s > 0.0f) ? 1 : 0;
    if (lane == 0) flg[warp] = act;
    __syncthreads();
    if (threadIdx.x == 0) {
        int tot = 0;
        for (int i = 0; i < 32; i++) { pre[i] = tot; tot += flg[i]; }
        flg[0] = atomicAdd(&g_cnt, tot);
    }
    __syncthreads();
    int slot = act ? (flg[0] + pre[warp]) : -1;
    if (lane == 0) g_slot[tok] = slot;
    if (act) {
        __half2* X = (__half2*)(g_X + (size_t)slot*512);
        X[lane*2+0]   = __floats2half2_rn(a0.x, a0.y);
        X[lane*2+1]   = __floats2half2_rn(a0.z, a0.w);
        X[64+lane*2]  = __floats2half2_rn(a1.x, a1.y);
        X[65+lane*2]  = __floats2half2_rn(a1.z, a1.w);
        X[128+lane*2] = __floats2half2_rn(b0.x, b0.y);
        X[129+lane*2] = __floats2half2_rn(b0.z, b0.w);
        X[192+lane*2] = __floats2half2_rn(b1.x, b1.y);
        X[193+lane*2] = __floats2half2_rn(b1.z, b1.w);
    }
}

__device__ __forceinline__ uint32_t s2u(const void* p) {
    uint32_t a;
    asm("{ .reg .u64 t; cvta.to.shared.u64 t, %1; cvt.u32.u64 %0, t; }" : "=r"(a) : "l"(p));
    return a;
}
#define CPA(d, s) asm volatile("cp.async.cg.shared.global [%0], [%1], 16;" :: "r"(d), "l"(s))
#define CPC() asm volatile("cp.async.commit_group;" ::: "memory")

// smem (halves): W ring | P (64x136) | C (64x264) | A stream (2 x 64x40)
#define OFFP 17408
#define OFFC 26112
#define OFFA 43008
#define SMEMB (48128*2)   // 96256 B -> 2 CTAs/SM

__device__ __forceinline__ void ldmA(uint32_t* a, uint32_t addr) {
    asm volatile("ldmatrix.sync.aligned.m8n8.x4.shared.b16 {%0,%1,%2,%3}, [%4];"
        : "=r"(a[0]), "=r"(a[1]), "=r"(a[2]), "=r"(a[3]) : "r"(addr));
}
__device__ __forceinline__ void ldmB4(uint32_t* b, uint32_t addr) {
    asm volatile("ldmatrix.sync.aligned.m8n8.x4.trans.shared.b16 {%0,%1,%2,%3}, [%4];"
        : "=r"(b[0]), "=r"(b[1]), "=r"(b[2]), "=r"(b[3]) : "r"(addr));
}
__device__ __forceinline__ void mma16816(float* d, const uint32_t* a,
                                         uint32_t b0, uint32_t b1) {
    asm volatile("mma.sync.aligned.m16n8k16.row.col.f32.f16.f16.f32 "
        "{%0,%1,%2,%3},{%4,%5,%6,%7},{%8,%9},{%0,%1,%2,%3};"
        : "+f"(d[0]), "+f"(d[1]), "+f"(d[2]), "+f"(d[3])
        : "r"(a[0]), "r"(a[1]), "r"(a[2]), "r"(a[3]), "r"(b0), "r"(b1));
}

__device__ __forceinline__ void epi_store(
    __half* sm, float d[2][4][4], const float* bias, int act,
    __half* dgm, int dOffH, int dLd, int mw, int nw, int lane)
{
    #pragma unroll
    for (int i = 0; i < 2; i++) {
        int row = mw + i*16 + (lane >> 2);
        #pragma unroll
        for (int j = 0; j < 4; j++) {
            int col = nw + j*8 + (lane & 3)*2;
            float2 bb = *(const float2*)&bias[col];
            float v0 = d[i][j][0] + bb.x, v1 = d[i][j][1] + bb.y;
            float v2 = d[i][j][2] + bb.x, v3 = d[i][j][3] + bb.y;
            if (act == 1) {
                v0 = fmaxf(v0,0.f); v1 = fmaxf(v1,0.f);
                v2 = fmaxf(v2,0.f); v3 = fmaxf(v3,0.f);
            } else if (act == 2) {
                v0 = 1.f/(1.f+__expf(-v0)); v1 = 1.f/(1.f+__expf(-v1));
                v2 = 1.f/(1.f+__expf(-v2)); v3 = 1.f/(1.f+__expf(-v3));
            }
            if (dgm) {
                *(__half2*)&dgm[(size_t)row*256 + col]     = __floats2half2_rn(v0, v1);
                *(__half2*)&dgm[(size_t)(row+8)*256 + col] = __floats2half2_rn(v2, v3);
            } else {
                *(__half2*)&sm[dOffH + row*dLd + col]     = __floats2half2_rn(v0, v1);
                *(__half2*)&sm[dOffH + (row+8)*dLd + col] = __floats2half2_rn(v2, v3);
            }
        }
    }
    __syncthreads();
}

// one GEMM layer with A resident in smem: out = act(A[64,K] @ W[:,0:128] + b)
__device__ __forceinline__ void phase_smemA(
    __half* sm, uint32_t sAu, int aOffH, int ldA, int nk,
    const __half* W, int Ws, const float* bias, int act,
    __half* dgm, int dOffH, int dLd,
    int tid, int lane, int mw, int nw, int aR, int aC)
{
    uint32_t aBase = sAu + (uint32_t)(aOffH + (mw + aR)*ldA + aC) * 2;
    uint32_t bPat  = sAu + (uint32_t)((lane & 15)*136 + nw + ((lane >> 4)*8)) * 2;
    float d[2][4][4];
    #pragma unroll
    for (int i = 0; i < 2; i++)
        #pragma unroll
        for (int j = 0; j < 4; j++)
            #pragma unroll
            for (int e = 0; e < 4; e++) d[i][j][e] = 0.0f;

    // full coverage: 64 rows x 128 cols = 1024 x 16B -> 4 iterations of 256 thr
    #define LWP(st, kc) do { int _k0 = (kc)*64;                                      \
        _Pragma("unroll")                                                            \
        for (int t = 0; t < 4; t++) {                                                \
            int idx = tid + t*256; int r = idx >> 4, c8 = (idx & 15)*8;              \
            CPA(sAu + ((st)*8704 + r*136 + c8)*2, W + (size_t)(_k0+r)*Ws + c8);      \
        } CPC(); } while (0)

    LWP(0, 0);
    for (int k = 0; k < nk; k++) {
        if (k + 1 < nk) { LWP((k+1) & 1, k+1);
            asm volatile("cp.async.wait_group 1;" ::: "memory");
        } else {
            asm volatile("cp.async.wait_group 0;" ::: "memory");
        }
        __syncthreads();
        uint32_t bS = bPat + ((k & 1) * 8704) * 2;
        #pragma unroll
        for (int kk = 0; kk < 4; kk++) {
            uint32_t af[2][4], bq[2][4];
            #pragma unroll
            for (int i = 0; i < 2; i++)
                ldmA(af[i], aBase + (i*16*ldA + k*64 + kk*16) * 2);
            #pragma unroll
            for (int jj = 0; jj < 2; jj++)
                ldmB4(bq[jj], bS + (kk*16*136 + jj*16) * 2);
            #pragma unroll
            for (int i = 0; i < 2; i++)
                #pragma unroll
                for (int jj = 0; jj < 2; jj++) {
                    mma16816(d[i][jj*2  ], af[i], bq[jj][0], bq[jj][1]);
                    mma16816(d[i][jj*2+1], af[i], bq[jj][2], bq[jj][3]);
                }
        }
        __syncthreads();
    }
    #undef LWP
    epi_store(sm, d, bias, act, dgm, dOffH, dLd, mw, nw, lane);
}

// full 4-layer chain per CTA: z=0 gate (X->G, sigmoid), z=1 value (hT->Cv, linear)
__global__ void __launch_bounds__(256,2) chain_k(
    const float* gb0, const float* gb1, const float* gb2, const float* gb3,
    const float* ob0, const float* ob1, const float* ob2, const float* ob3)
{
    extern __shared__ __half sm[];
    int m0 = blockIdx.x * 64;
    if (m0 >= g_cnt) return;
    const int chain = blockIdx.z;
    const int tid = threadIdx.x, warp = tid >> 5, lane = tid & 31;
    const int mw = (warp >> 2) * 32, nw = (warp & 3) * 32;
    const int aR = (lane & 7) + ((lane & 8) ? 8 : 0);
    const int aC = (lane & 16) ? 8 : 0;
    const uint32_t sAu = s2u(sm);

    const float* b0 = chain ? ob0 : gb0;
    const float* b1 = chain ? ob1 : gb1;
    const float* b2 = chain ? ob2 : gb2;
    const float* b3 = chain ? ob3 : gb3;
    const __half* W0 = g_w + (chain ? 163840 : 0);
    const __half* W1 = g_w + (chain ? 196608 : 65536);
    const __half* W2 = g_w + (chain ? 229376 : 98304);
    const __half* W3 = g_w + (chain ? 262144 : 131072);
    const __half* Ag = g_X + (size_t)m0*512 + (chain ? 256 : 0);
    const int nkA = chain ? 8 : 16;   // K/32
    __half* outg = (chain ? g_Cv : g_G) + (size_t)m0*256;
    const int actF = chain ? 0 : 2;

    // ---- L0: stream A (BK=32) from gmem, W0 K x 128 -> P, relu ----
    {
        float d[2][4][4];
        #pragma unroll
        for (int i = 0; i < 2; i++)
            #pragma unroll
            for (int j = 0; j < 4; j++)
                #pragma unroll
                for (int e = 0; e < 4; e++) d[i][j][e] = 0.0f;

        // A chunk 64x32 = 256x16B (1 pass); W chunk 32x128 = 512x16B (2 passes)
        #define LOADS(st, kc) do { int _k0 = (kc)*32;                                \
            { int r = tid >> 2, c8 = (tid & 3)*8;                                    \
              CPA(sAu + (OFFA + (st)*2560 + r*40 + c8)*2,                            \
                  Ag + (size_t)r*512 + _k0 + c8); }                                  \
            _Pragma("unroll")                                                        \
            for (int t = 0; t < 2; t++) {                                            \
                int idx = tid + t*256; int r = idx >> 4, c8 = (idx & 15)*8;          \
                CPA(sAu + ((st)*4352 + r*136 + c8)*2,                                \
                    W0 + (size_t)(_k0+r)*128 + c8); }                                \
            CPC(); } while (0)

        const uint32_t aBs = sAu + (uint32_t)(OFFA + (mw + aR)*40 + aC) * 2;
        const uint32_t bPat = sAu + (uint32_t)((lane & 15)*136 + nw + ((lane >> 4)*8)) * 2;

        LOADS(0, 0);
        for (int k = 0; k < nkA; k++) {
            if (k + 1 < nkA) { LOADS((k+1) & 1, k+1);
                asm volatile("cp.async.wait_group 1;" ::: "memory");
            } else {
                asm volatile("cp.async.wait_group 0;" ::: "memory");
            }
            __syncthreads();
            const uint32_t aS = aBs + ((k & 1) * 2560) * 2;
            const uint32_t bS = bPat + ((k & 1) * 4352) * 2;
            #pragma unroll
            for (int kk = 0; kk < 2; kk++) {
                uint32_t af[2][4], bq[2][4];
                #pragma unroll
                for (int i = 0; i < 2; i++)
                    ldmA(af[i], aS + (i*16*40 + kk*16) * 2);
                #pragma unroll
                for (int jj = 0; jj < 2; jj++)
                    ldmB4(bq[jj], bS + (kk*16*136 + jj*16) * 2);
                #pragma unroll
                for (int i = 0; i < 2; i++)
                    #pragma unroll
                    for (int jj = 0; jj < 2; jj++) {
                        mma16816(d[i][jj*2  ], af[i], bq[jj][0], bq[jj][1]);
                        mma16816(d[i][jj*2+1], af[i], bq[jj][2], bq[jj][3]);
                    }
            }
            __syncthreads();
        }
        #undef LOADS
        epi_store(sm, d, b0, 1, nullptr, OFFP, 136, mw, nw, lane);
    }

    // ---- L1: P (K=128) @ W1[128x256] -> C, relu (2 col passes) ----
    phase_smemA(sm, sAu, OFFP, 136, 2, W1,       256, b1,       1, nullptr, OFFC,       264, tid, lane, mw, nw, aR, aC);
    phase_smemA(sm, sAu, OFFP, 136, 2, W1 + 128, 256, b1 + 128, 1, nullptr, OFFC + 128, 264, tid, lane, mw, nw, aR, aC);
    // ---- L2: C (K=256) @ W2[256x128] -> P, relu ----
    phase_smemA(sm, sAu, OFFC, 264, 4, W2, 128, b2, 1, nullptr, OFFP, 136, tid, lane, mw, nw, aR, aC);
    // ---- L3: P (K=128) @ W3[128x256] -> gmem out, act ----
    phase_smemA(sm, sAu, OFFP, 136, 2, W3,       256, b3,       actF, outg,       0, 0, tid, lane, mw, nw, aR, aC);
    phase_smemA(sm, sAu, OFFP, 136, 2, W3 + 128, 256, b3 + 128, actF, outg + 128, 0, 0, tid, lane, mw, nw, aR, aC);
}

__global__ void __launch_bounds__(512) reduce_k(float* __restrict__ out)
{
    __shared__ float2 part[4][128];
    const int b = blockIdx.x, tx = threadIdx.x, ty = threadIdx.y;
    const int* __restrict__ sl = g_slot + b*NTOK + ty*64;
    float2 acc = make_float2(0.f, 0.f);
    #pragma unroll 8
    for (int t = 0; t < 64; t++) {
        int s = sl[t];
        if (s >= 0) {
            float2 fg = __half22float2(*(const __half2*)&g_G [(size_t)s*256 + 2*tx]);
            float2 fv = __half22float2(*(const __half2*)&g_Cv[(size_t)s*256 + 2*tx]);
            acc.x += fg.x * fv.x;
            acc.y += fg.y * fv.y;
        }
    }
    part[ty][tx] = acc;
    __syncthreads();
    if (ty == 0) {
        float2 r = part[0][tx];
        #pragma unroll
        for (int g = 1; g < 4; g++) { r.x += part[g][tx].x; r.y += part[g][tx].y; }
        *(float2*)&out[b*256 + 2*tx] = r;
    }
}

extern "C" void kernel_launch(void* const* d_in, const int* in_sizes, int n_in,
                              void* d_out, int out_size)
{
    const float* h0 = (const float*)d_in[0];
    const float* hT = (const float*)d_in[1];
    const float* W[8]  = { (const float*)d_in[2],  (const float*)d_in[4],
                           (const float*)d_in[6],  (const float*)d_in[8],
                           (const float*)d_in[10], (const float*)d_in[12],
                           (const float*)d_in[14], (const float*)d_in[16] };
    const float* bs[8] = { (const float*)d_in[3],  (const float*)d_in[5],
                           (const float*)d_in[7],  (const float*)d_in[9],
                           (const float*)d_in[11], (const float*)d_in[13],
                           (const float*)d_in[15], (const float*)d_in[17] };
    float* out = (float*)d_out;

    convert_w<<<(294912+255)/256, 256>>>(W[0],W[1],W[2],W[3],W[4],W[5],W[6],W[7]);
    stage1<<<MTOT/32, 1024>>>(h0, hT);

    cudaFuncSetAttribute(chain_k, cudaFuncAttributeMaxDynamicSharedMemorySize, SMEMB);
    chain_k<<<dim3(MTOT/64, 1, 2), 256, SMEMB>>>(
        bs[0], bs[1], bs[2], bs[3], bs[4], bs[5], bs[6], bs[7]);

    reduce_k<<<BATCH, dim3(128,4)>>>(out);
}

// round 15
// speedup vs baseline: 1.0169x; 1.0169x over previous
#include <cuda_runtime.h>
#include <cuda_fp16.h>
#include <cstdint>

#define BATCH 512
#define NTOK  256
#define MTOT  (BATCH*NTOK)
#define NTILE (MTOT/128)

__device__ __half g_w[294912];
__device__ __half g_X [(size_t)MTOT*512];
__device__ __half g_Cg[(size_t)MTOT*256];
__device__ __half g_Cv[(size_t)MTOT*256];
__device__ __half g_G [(size_t)MTOT*256];
__device__ int    g_slot[MTOT];
__device__ int    g_cnt;
__device__ __half* g_bufs[4];

__constant__ int WOFF[9] = {0,65536,98304,131072,163840,196608,229376,262144,294912};

__global__ void convert_w(const float* w0,const float* w1,const float* w2,const float* w3,
                          const float* w4,const float* w5,const float* w6,const float* w7)
{
    int i = blockIdx.x*blockDim.x + threadIdx.x;
    if (i == 0) {
        g_cnt = 0;
        g_bufs[0]=g_X; g_bufs[1]=g_Cg; g_bufs[2]=g_Cv; g_bufs[3]=g_G;
    }
    if (i >= 294912) return;
    const float* p[8] = {w0,w1,w2,w3,w4,w5,w6,w7};
    int s = 0;
    while (i >= WOFF[s+1]) s++;
    g_w[i] = __float2half_rn(p[s][i - WOFF[s]]);
}

__global__ void __launch_bounds__(1024) stage1(const float* __restrict__ h0,
                                               const float* __restrict__ hT)
{
    __shared__ int flg[32], pre[32];
    int warp = threadIdx.x >> 5, lane = threadIdx.x & 31;
    int tok = blockIdx.x*32 + warp;
    const float4* p0 = (const float4*)(h0 + (size_t)tok*256);
    const float4* p1 = (const float4*)(hT + (size_t)tok*256);
    float4 a0 = p0[lane], a1 = p0[lane+32];
    float4 b0 = p1[lane], b1 = p1[lane+32];
    float s = a0.x+a0.y+a0.z+a0.w + a1.x+a1.y+a1.z+a1.w;
    #pragma unroll
    for (int o = 16; o > 0; o >>= 1) s += __shfl_xor_sync(0xffffffffu, s, o);
    int act = (s > 0.0f) ? 1 : 0;
    if (lane == 0) flg[warp] = act;
    __syncthreads();
    if (threadIdx.x == 0) {
        int tot = 0;
        for (int i = 0; i < 32; i++) { pre[i] = tot; tot += flg[i]; }
        flg[0] = atomicAdd(&g_cnt, tot);
    }
    __syncthreads();
    int slot = act ? (flg[0] + pre[warp]) : -1;
    if (lane == 0) g_slot[tok] = slot;
    if (act) {
        __half2* X = (__half2*)(g_X + (size_t)slot*512);
        X[lane*2+0]   = __floats2half2_rn(a0.x, a0.y);
        X[lane*2+1]   = __floats2half2_rn(a0.z, a0.w);
        X[64+lane*2]  = __floats2half2_rn(a1.x, a1.y);
        X[65+lane*2]  = __floats2half2_rn(a1.z, a1.w);
        X[128+lane*2] = __floats2half2_rn(b0.x, b0.y);
        X[129+lane*2] = __floats2half2_rn(b0.z, b0.w);
        X[192+lane*2] = __floats2half2_rn(b1.x, b1.y);
        X[193+lane*2] = __floats2half2_rn(b1.z, b1.w);
    }
}

__device__ __forceinline__ uint32_t s2u(const void* p) {
    uint32_t a;
    asm("{ .reg .u64 t; cvta.to.shared.u64 t, %1; cvt.u32.u64 %0, t; }" : "=r"(a) : "l"(p));
    return a;
}
#define CPA(d, s) asm volatile("cp.async.cg.shared.global [%0], [%1], 16;" :: "r"(d), "l"(s))
#define CPC() asm volatile("cp.async.commit_group;" ::: "memory")

#define LDA_S 72
#define LDB_S 136
#define LDU   136
#define SA_H  (128*LDA_S)
#define SB_H  (64*LDB_S)
#define OFF_B (2*SA_H)
#define OFF_U (2*SA_H + 2*SB_H)
#define SMEMB ((2*SA_H + 2*SB_H + 128*LDU)*2)

__device__ __forceinline__ void ldmA(uint32_t* a, uint32_t addr) {
    asm volatile("ldmatrix.sync.aligned.m8n8.x4.shared.b16 {%0,%1,%2,%3}, [%4];"
        : "=r"(a[0]), "=r"(a[1]), "=r"(a[2]), "=r"(a[3]) : "r"(addr));
}
__device__ __forceinline__ void ldmB4(uint32_t* b, uint32_t addr) {
    asm volatile("ldmatrix.sync.aligned.m8n8.x4.trans.shared.b16 {%0,%1,%2,%3}, [%4];"
        : "=r"(b[0]), "=r"(b[1]), "=r"(b[2]), "=r"(b[3]) : "r"(addr));
}
__device__ __forceinline__ void mma16816(float* d, const uint32_t* a,
                                         uint32_t b0, uint32_t b1) {
    asm volatile("mma.sync.aligned.m16n8k16.row.col.f32.f16.f16.f32 "
        "{%0,%1,%2,%3},{%4,%5,%6,%7},{%8,%9},{%0,%1,%2,%3};"
        : "+f"(d[0]), "+f"(d[1]), "+f"(d[2]), "+f"(d[3])
        : "r"(a[0]), "r"(a[1]), "r"(a[2]), "r"(a[3]), "r"(b0), "r"(b1));
}

// Fused two layers: Y = relu(A[128,K1] @ W1[K1,128] + b1) kept in smem,
// then Out[:, 0:256] = act2(Y @ W2[128,256] + b2) written to gmem.
__global__ void __launch_bounds__(256,2) fused2_k(
    int asel0, int aoff0, int lda0, int K10, int w1o0, const float* b1p0,
    int w2o0, const float* b2p0, int act20, int osel0,
    int asel1, int aoff1, int lda1, int K11, int w1o1, const float* b1p1,
    int w2o1, const float* b2p1, int act21, int osel1)
{
    extern __shared__ __half sm[];
    int m0 = blockIdx.x * 128;
    if (m0 >= g_cnt) return;

    int asel, aoff, lda, K1, w1o, w2o, act2, osel;
    const float *b1p, *b2p;
    if (blockIdx.z == 0) { asel=asel0; aoff=aoff0; lda=lda0; K1=K10; w1o=w1o0; b1p=b1p0;
                           w2o=w2o0; b2p=b2p0; act2=act20; osel=osel0; }
    else                 { asel=asel1; aoff=aoff1; lda=lda1; K1=K11; w1o=w1o1; b1p=b1p1;
                           w2o=w2o1; b2p=b2p1; act2=act21; osel=osel1; }

    const __half* __restrict__ A  = g_bufs[asel] + (size_t)m0*lda + aoff;
    const __half* __restrict__ W1 = g_w + w1o;
    const __half* __restrict__ W2 = g_w + w2o;
    __half* __restrict__ Co = g_bufs[osel];

    const int tid = threadIdx.x, warp = tid >> 5, lane = tid & 31;
    const int mw = (warp >> 2) * 64;
    const int nw = (warp & 3) * 32;
    const uint32_t sAu = s2u(sm);
    const uint32_t sBu = sAu + OFF_B*2;
    const uint32_t sUu = sAu + OFF_U*2;

    const uint32_t aRow = mw + (lane & 7) + ((lane & 8) ? 8 : 0);
    const uint32_t aCol = (lane & 16) ? 8 : 0;
    const uint32_t aBase  = sAu + (aRow * LDA_S + aCol) * 2;
    const uint32_t aUBase = sUu + (aRow * LDU   + aCol) * 2;
    const uint32_t bBase  = sBu + ((lane & 15) * LDB_S + nw + (lane >> 4) * 8) * 2;

    float d[4][4][4];
    #pragma unroll
    for (int i = 0; i < 4; i++)
        #pragma unroll
        for (int j = 0; j < 4; j++)
            #pragma unroll
            for (int e = 0; e < 4; e++) d[i][j][e] = 0.0f;

    // ---------------- phase 1: A(gmem) @ W1 -> U(smem), relu ----------------
    const int nk1 = K1 >> 6;

    #define LOAD_P1(st, kc) do {                                                     \
        int _k0 = (kc) * 64;                                                         \
        _Pragma("unroll")                                                            \
        for (int t = 0; t < 4; t++) {                                                \
            int idx = tid + t*256;                                                   \
            int r = idx >> 3, c8 = (idx & 7) * 8;                                    \
            CPA(sAu + ((st)*SA_H + r*LDA_S + c8)*2, A + (size_t)r*lda + _k0 + c8);   \
        }                                                                            \
        _Pragma("unroll")                                                            \
        for (int t = 0; t < 4; t++) {                                                \
            int idx = tid + t*256;                                                   \
            int r = idx >> 4, c8 = (idx & 15) * 8;                                   \
            CPA(sBu + ((st)*SB_H + r*LDB_S + c8)*2, W1 + (size_t)(_k0+r)*128 + c8);  \
        }                                                                            \
        CPC();                                                                       \
    } while (0)

    LOAD_P1(0, 0);
    for (int k = 0; k < nk1; k++) {
        if (k + 1 < nk1) {
            LOAD_P1((k+1) & 1, k+1);
            asm volatile("cp.async.wait_group 1;" ::: "memory");
        } else {
            asm volatile("cp.async.wait_group 0;" ::: "memory");
        }
        __syncthreads();
        const uint32_t aS = aBase + ((k & 1) * SA_H) * 2;
        const uint32_t bS = bBase + ((k & 1) * SB_H) * 2;
        // software-pipelined B fragments (one kk ahead)
        uint32_t bq[2][2][4];
        #pragma unroll
        for (int jj = 0; jj < 2; jj++)
            ldmB4(bq[0][jj], bS + (jj*16) * 2);
        #pragma unroll
        for (int kk = 0; kk < 4; kk++) {
            if (kk < 3) {
                #pragma unroll
                for (int jj = 0; jj < 2; jj++)
                    ldmB4(bq[(kk+1)&1][jj], bS + ((kk+1)*16*LDB_S + jj*16) * 2);
            }
            uint32_t af[4][4];
            #pragma unroll
            for (int i = 0; i < 4; i++)
                ldmA(af[i], aS + (i*16*LDA_S + kk*16) * 2);
            #pragma unroll
            for (int i = 0; i < 4; i++)
                #pragma unroll
                for (int jj = 0; jj < 2; jj++) {
                    mma16816(d[i][jj*2  ], af[i], bq[kk&1][jj][0], bq[kk&1][jj][1]);
                    mma16816(d[i][jj*2+1], af[i], bq[kk&1][jj][2], bq[kk&1][jj][3]);
                }
        }
        __syncthreads();
    }

    // phase-1 epilogue: bias + relu -> U (smem)
    #pragma unroll
    for (int i = 0; i < 4; i++) {
        int row = mw + i*16 + (lane >> 2);
        #pragma unroll
        for (int j = 0; j < 4; j++) {
            int col = nw + j*8 + (lane & 3)*2;
            float2 bb = *(const float2*)&b1p[col];
            float v0 = fmaxf(d[i][j][0] + bb.x, 0.f);
            float v1 = fmaxf(d[i][j][1] + bb.y, 0.f);
            float v2 = fmaxf(d[i][j][2] + bb.x, 0.f);
            float v3 = fmaxf(d[i][j][3] + bb.y, 0.f);
            *(__half2*)&sm[OFF_U + row*LDU + col]     = __floats2half2_rn(v0, v1);
            *(__half2*)&sm[OFF_U + (row+8)*LDU + col] = __floats2half2_rn(v2, v3);
        }
    }
    __syncthreads();

    // ---------------- phase 2: U(smem) @ W2 -> Co(gmem), act2, N2=256 --------
    #define LOAD_P2(st, kc, pp) do {                                                 \
        int _k0 = (kc) * 64;                                                         \
        _Pragma("unroll")                                                            \
        for (int t = 0; t < 4; t++) {                                                \
            int idx = tid + t*256;                                                   \
            int r = idx >> 4, c8 = (idx & 15) * 8;                                   \
            CPA(sBu + ((st)*SB_H + r*LDB_S + c8)*2,                                  \
                W2 + (size_t)(_k0+r)*256 + (pp)*128 + c8);                           \
        }                                                                            \
        CPC();                                                                       \
    } while (0)

    for (int p = 0; p < 2; p++) {
        #pragma unroll
        for (int i = 0; i < 4; i++)
            #pragma unroll
            for (int j = 0; j < 4; j++)
                #pragma unroll
                for (int e = 0; e < 4; e++) d[i][j][e] = 0.0f;

        LOAD_P2(0, 0, p);
        for (int k = 0; k < 2; k++) {
            if (k == 0) {
                LOAD_P2(1, 1, p);
                asm volatile("cp.async.wait_group 1;" ::: "memory");
            } else {
                asm volatile("cp.async.wait_group 0;" ::: "memory");
            }
            __syncthreads();
            const uint32_t bS = bBase + (k * SB_H) * 2;
            uint32_t bq[2][2][4];
            #pragma unroll
            for (int jj = 0; jj < 2; jj++)
                ldmB4(bq[0][jj], bS + (jj*16) * 2);
            #pragma unroll
            for (int kk = 0; kk < 4; kk++) {
                if (kk < 3) {
                    #pragma unroll
                    for (int jj = 0; jj < 2; jj++)
                        ldmB4(bq[(kk+1)&1][jj], bS + ((kk+1)*16*LDB_S + jj*16) * 2);
                }
                uint32_t af[4][4];
                #pragma unroll
                for (int i = 0; i < 4; i++)
                    ldmA(af[i], aUBase + (i*16*LDU + k*64 + kk*16) * 2);
                #pragma unroll
                for (int i = 0; i < 4; i++)
                    #pragma unroll
                    for (int jj = 0; jj < 2; jj++) {
                        mma16816(d[i][jj*2  ], af[i], bq[kk&1][jj][0], bq[kk&1][jj][1]);
                        mma16816(d[i][jj*2+1], af[i], bq[kk&1][jj][2], bq[kk&1][jj][3]);
                    }
            }
            __syncthreads();
        }

        #pragma unroll
        for (int i = 0; i < 4; i++) {
            int row = m0 + mw + i*16 + (lane >> 2);
            #pragma unroll
            for (int j = 0; j < 4; j++) {
                int gcol = p*128 + nw + j*8 + (lane & 3)*2;
                float2 bb = *(const float2*)&b2p[gcol];
                float v0 = d[i][j][0] + bb.x, v1 = d[i][j][1] + bb.y;
                float v2 = d[i][j][2] + bb.x, v3 = d[i][j][3] + bb.y;
                if (act2 == 1) {
                    v0 = fmaxf(v0,0.f); v1 = fmaxf(v1,0.f);
                    v2 = fmaxf(v2,0.f); v3 = fmaxf(v3,0.f);
                } else if (act2 == 2) {
                    v0 = 1.f/(1.f+__expf(-v0)); v1 = 1.f/(1.f+__expf(-v1));
                    v2 = 1.f/(1.f+__expf(-v2)); v3 = 1.f/(1.f+__expf(-v3));
                }
                *(__half2*)&Co[(size_t)row*256 + gcol]     = __floats2half2_rn(v0, v1);
                *(__half2*)&Co[(size_t)(row+8)*256 + gcol] = __floats2half2_rn(v2, v3);
            }
        }
    }
}

__global__ void __launch_bounds__(512) reduce_k(float* __restrict__ out)
{
    __shared__ float2 part[4][128];
    const int b = blockIdx.x, tx = threadIdx.x, ty = threadIdx.y;
    const int* __restrict__ sl = g_slot + b*NTOK + ty*64;
    float2 acc = make_float2(0.f, 0.f);
    #pragma unroll 8
    for (int t = 0; t < 64; t++) {
        int s = sl[t];
        if (s >= 0) {
            float2 fg = __half22float2(*(const __half2*)&g_G [(size_t)s*256 + 2*tx]);
            float2 fv = __half22float2(*(const __half2*)&g_Cv[(size_t)s*256 + 2*tx]);
            acc.x += fg.x * fv.x;
            acc.y += fg.y * fv.y;
        }
    }
    part[ty][tx] = acc;
    __syncthreads();
    if (ty == 0) {
        float2 r = part[0][tx];
        #pragma unroll
        for (int g = 1; g < 4; g++) { r.x += part[g][tx].x; r.y += part[g][tx].y; }
        *(float2*)&out[b*256 + 2*tx] = r;
    }
}

extern "C" void kernel_launch(void* const* d_in, const int* in_sizes, int n_in,
                              void* d_out, int out_size)
{
    const float* h0 = (const float*)d_in[0];
    const float* hT = (const float*)d_in[1];
    const float* W[8]  = { (const float*)d_in[2],  (const float*)d_in[4],
                           (const float*)d_in[6],  (const float*)d_in[8],
                           (const float*)d_in[10], (const float*)d_in[12],
                           (const float*)d_in[14], (const float*)d_in[16] };
    const float* bs[8] = { (const float*)d_in[3],  (const float*)d_in[5],
                           (const float*)d_in[7],  (const float*)d_in[9],
                           (const float*)d_in[11], (const float*)d_in[13],
                           (const float*)d_in[15], (const float*)d_in[17] };
    float* out = (float*)d_out;

    convert_w<<<(294912+255)/256, 256>>>(W[0],W[1],W[2],W[3],W[4],W[5],W[6],W[7]);
    stage1<<<MTOT/32, 1024>>>(h0, hT);

    cudaFuncSetAttribute(fused2_k, cudaFuncAttributeMaxDynamicSharedMemorySize, SMEMB);

    // launch 1: gate L0+L1 (X -> Cg), value L0+L1 (X.hT -> Cv)
    fused2_k<<<dim3(NTILE,1,2), 256, SMEMB>>>(
        0,   0, 512, 512,      0, bs[0],  65536, bs[1], 1, 1,
        0, 256, 512, 256, 163840, bs[4], 196608, bs[5], 1, 2);
    // launch 2: gate L2+L3 (Cg -> G, sigmoid), value L2+L3 (Cv -> Cv, linear)
    fused2_k<<<dim3(NTILE,1,2), 256, SMEMB>>>(
        1, 0, 256, 256,  98304, bs[2], 131072, bs[3], 2, 3,
        2, 0, 256, 256, 229376, bs[6], 262144, bs[7], 0, 2);

    reduce_k<<<BATCH, dim3(128,4)>>>(out);
}

// round 16
// speedup vs baseline: 1.0260x; 1.0089x over previous
#include <cuda_runtime.h>
#include <cuda_fp16.h>
#include <cstdint>

#define BATCH 512
#define NTOK  256
#define MTOT  (BATCH*NTOK)
#define NTILE (MTOT/128)

__device__ __half g_w[294912];
__device__ __half g_X [(size_t)MTOT*512];
__device__ __half g_Cg[(size_t)MTOT*256];
__device__ __half g_Cv[(size_t)MTOT*256];
__device__ __half g_G [(size_t)MTOT*256];
__device__ int    g_slot[MTOT];
__device__ int    g_cnt;          // zero at module load; reset by reduce_k each run
__device__ __half* g_bufs[4];

__constant__ int WOFF[9] = {0,65536,98304,131072,163840,196608,229376,262144,294912};

// stage1: mask + compaction + fp16 X materialization + weight conversion (folded in)
__global__ void __launch_bounds__(1024) stage1(
    const float* __restrict__ h0, const float* __restrict__ hT,
    const float* w0, const float* w1, const float* w2, const float* w3,
    const float* w4, const float* w5, const float* w6, const float* w7)
{
    __shared__ int flg[32], pre[32];
    int warp = threadIdx.x >> 5, lane = threadIdx.x & 31;
    int tok = blockIdx.x*32 + warp;

    // folded weight conversion: 72 elements per block (294912 / 4096)
    {
        int wi = blockIdx.x*72 + threadIdx.x;
        if (threadIdx.x < 72 && wi < 294912) {
            const float* p[8] = {w0,w1,w2,w3,w4,w5,w6,w7};
            int s = 0;
            while (wi >= WOFF[s+1]) s++;
            g_w[wi] = __float2half_rn(p[s][wi - WOFF[s]]);
        }
        if (threadIdx.x == 0) {
            g_bufs[0]=g_X; g_bufs[1]=g_Cg; g_bufs[2]=g_Cv; g_bufs[3]=g_G;
        }
    }

    const float4* p0 = (const float4*)(h0 + (size_t)tok*256);
    const float4* p1 = (const float4*)(hT + (size_t)tok*256);
    float4 a0 = p0[lane], a1 = p0[lane+32];
    float4 b0 = p1[lane], b1 = p1[lane+32];
    float s = a0.x+a0.y+a0.z+a0.w + a1.x+a1.y+a1.z+a1.w;
    #pragma unroll
    for (int o = 16; o > 0; o >>= 1) s += __shfl_xor_sync(0xffffffffu, s, o);
    int act = (s > 0.0f) ? 1 : 0;
    if (lane == 0) flg[warp] = act;
    __syncthreads();
    if (threadIdx.x == 0) {
        int tot = 0;
        for (int i = 0; i < 32; i++) { pre[i] = tot; tot += flg[i]; }
        flg[0] = atomicAdd(&g_cnt, tot);
    }
    __syncthreads();
    int slot = act ? (flg[0] + pre[warp]) : -1;
    if (lane == 0) g_slot[tok] = slot;
    if (act) {
        __half2* X = (__half2*)(g_X + (size_t)slot*512);
        X[lane*2+0]   = __floats2half2_rn(a0.x, a0.y);
        X[lane*2+1]   = __floats2half2_rn(a0.z, a0.w);
        X[64+lane*2]  = __floats2half2_rn(a1.x, a1.y);
        X[65+lane*2]  = __floats2half2_rn(a1.z, a1.w);
        X[128+lane*2] = __floats2half2_rn(b0.x, b0.y);
        X[129+lane*2] = __floats2half2_rn(b0.z, b0.w);
        X[192+lane*2] = __floats2half2_rn(b1.x, b1.y);
        X[193+lane*2] = __floats2half2_rn(b1.z, b1.w);
    }
}

__device__ __forceinline__ uint32_t s2u(const void* p) {
    uint32_t a;
    asm("{ .reg .u64 t; cvta.to.shared.u64 t, %1; cvt.u32.u64 %0, t; }" : "=r"(a) : "l"(p));
    return a;
}
#define CPA(d, s) asm volatile("cp.async.cg.shared.global [%0], [%1], 16;" :: "r"(d), "l"(s))
#define CPC() asm volatile("cp.async.commit_group;" ::: "memory")

#define LDA_S 72
#define LDB_S 136
#define LDU   136
#define SA_H  (128*LDA_S)
#define SB_H  (64*LDB_S)
#define OFF_B (2*SA_H)
#define OFF_U (2*SA_H + 2*SB_H)
#define SMEMB ((2*SA_H + 2*SB_H + 128*LDU)*2)

__device__ __forceinline__ void ldmA(uint32_t* a, uint32_t addr) {
    asm volatile("ldmatrix.sync.aligned.m8n8.x4.shared.b16 {%0,%1,%2,%3}, [%4];"
        : "=r"(a[0]), "=r"(a[1]), "=r"(a[2]), "=r"(a[3]) : "r"(addr));
}
__device__ __forceinline__ void ldmB4(uint32_t* b, uint32_t addr) {
    asm volatile("ldmatrix.sync.aligned.m8n8.x4.trans.shared.b16 {%0,%1,%2,%3}, [%4];"
        : "=r"(b[0]), "=r"(b[1]), "=r"(b[2]), "=r"(b[3]) : "r"(addr));
}
__device__ __forceinline__ void mma16816(float* d, const uint32_t* a,
                                         uint32_t b0, uint32_t b1) {
    asm volatile("mma.sync.aligned.m16n8k16.row.col.f32.f16.f16.f32 "
        "{%0,%1,%2,%3},{%4,%5,%6,%7},{%8,%9},{%0,%1,%2,%3};"
        : "+f"(d[0]), "+f"(d[1]), "+f"(d[2]), "+f"(d[3])
        : "r"(a[0]), "r"(a[1]), "r"(a[2]), "r"(a[3]), "r"(b0), "r"(b1));
}

// Fused two layers: Y = relu(A[128,K1] @ W1[K1,128] + b1) kept in smem,
// then Out[:, 0:256] = act2(Y @ W2[128,256] + b2) written to gmem.
__global__ void __launch_bounds__(256,2) fused2_k(
    int asel0, int aoff0, int lda0, int K10, int w1o0, const float* b1p0,
    int w2o0, const float* b2p0, int act20, int osel0,
    int asel1, int aoff1, int lda1, int K11, int w1o1, const float* b1p1,
    int w2o1, const float* b2p1, int act21, int osel1)
{
    extern __shared__ __half sm[];
    int m0 = blockIdx.x * 128;
    if (m0 >= g_cnt) return;

    int asel, aoff, lda, K1, w1o, w2o, act2, osel;
    const float *b1p, *b2p;
    if (blockIdx.z == 0) { asel=asel0; aoff=aoff0; lda=lda0; K1=K10; w1o=w1o0; b1p=b1p0;
                           w2o=w2o0; b2p=b2p0; act2=act20; osel=osel0; }
    else                 { asel=asel1; aoff=aoff1; lda=lda1; K1=K11; w1o=w1o1; b1p=b1p1;
                           w2o=w2o1; b2p=b2p1; act2=act21; osel=osel1; }

    const __half* __restrict__ A  = g_bufs[asel] + (size_t)m0*lda + aoff;
    const __half* __restrict__ W1 = g_w + w1o;
    const __half* __restrict__ W2 = g_w + w2o;
    __half* __restrict__ Co = g_bufs[osel];

    const int tid = threadIdx.x, warp = tid >> 5, lane = tid & 31;
    const int mw = (warp >> 2) * 64;
    const int nw = (warp & 3) * 32;
    const uint32_t sAu = s2u(sm);
    const uint32_t sBu = sAu + OFF_B*2;
    const uint32_t sUu = sAu + OFF_U*2;

    const uint32_t aRow = mw + (lane & 7) + ((lane & 8) ? 8 : 0);
    const uint32_t aCol = (lane & 16) ? 8 : 0;
    const uint32_t aBase  = sAu + (aRow * LDA_S + aCol) * 2;
    const uint32_t aUBase = sUu + (aRow * LDU   + aCol) * 2;
    const uint32_t bBase  = sBu + ((lane & 15) * LDB_S + nw + (lane >> 4) * 8) * 2;

    float d[4][4][4];
    #pragma unroll
    for (int i = 0; i < 4; i++)
        #pragma unroll
        for (int j = 0; j < 4; j++)
            #pragma unroll
            for (int e = 0; e < 4; e++) d[i][j][e] = 0.0f;

    // ---------------- phase 1: A(gmem) @ W1 -> U(smem), relu ----------------
    const int nk1 = K1 >> 6;

    #define LOAD_P1(st, kc) do {                                                     \
        int _k0 = (kc) * 64;                                                         \
        _Pragma("unroll")                                                            \
        for (int t = 0; t < 4; t++) {                                                \
            int idx = tid + t*256;                                                   \
            int r = idx >> 3, c8 = (idx & 7) * 8;                                    \
            CPA(sAu + ((st)*SA_H + r*LDA_S + c8)*2, A + (size_t)r*lda + _k0 + c8);   \
        }                                                                            \
        _Pragma("unroll")                                                            \
        for (int t = 0; t < 4; t++) {                                                \
            int idx = tid + t*256;                                                   \
            int r = idx >> 4, c8 = (idx & 15) * 8;                                   \
            CPA(sBu + ((st)*SB_H + r*LDB_S + c8)*2, W1 + (size_t)(_k0+r)*128 + c8);  \
        }                                                                            \
        CPC();                                                                       \
    } while (0)

    LOAD_P1(0, 0);
    for (int k = 0; k < nk1; k++) {
        if (k + 1 < nk1) {
            LOAD_P1((k+1) & 1, k+1);
            asm volatile("cp.async.wait_group 1;" ::: "memory");
        } else {
            asm volatile("cp.async.wait_group 0;" ::: "memory");
        }
        __syncthreads();
        const uint32_t aS = aBase + ((k & 1) * SA_H) * 2;
        const uint32_t bS = bBase + ((k & 1) * SB_H) * 2;
        uint32_t bq[2][2][4];
        #pragma unroll
        for (int jj = 0; jj < 2; jj++)
            ldmB4(bq[0][jj], bS + (jj*16) * 2);
        #pragma unroll
        for (int kk = 0; kk < 4; kk++) {
            if (kk < 3) {
                #pragma unroll
                for (int jj = 0; jj < 2; jj++)
                    ldmB4(bq[(kk+1)&1][jj], bS + ((kk+1)*16*LDB_S + jj*16) * 2);
            }
            uint32_t af[4][4];
            #pragma unroll
            for (int i = 0; i < 4; i++)
                ldmA(af[i], aS + (i*16*LDA_S + kk*16) * 2);
            #pragma unroll
            for (int i = 0; i < 4; i++)
                #pragma unroll
                for (int jj = 0; jj < 2; jj++) {
                    mma16816(d[i][jj*2  ], af[i], bq[kk&1][jj][0], bq[kk&1][jj][1]);
                    mma16816(d[i][jj*2+1], af[i], bq[kk&1][jj][2], bq[kk&1][jj][3]);
                }
        }
        __syncthreads();
    }

    // phase-1 epilogue: bias + relu -> U (smem)
    #pragma unroll
    for (int i = 0; i < 4; i++) {
        int row = mw + i*16 + (lane >> 2);
        #pragma unroll
        for (int j = 0; j < 4; j++) {
            int col = nw + j*8 + (lane & 3)*2;
            float2 bb = *(const float2*)&b1p[col];
            float v0 = fmaxf(d[i][j][0] + bb.x, 0.f);
            float v1 = fmaxf(d[i][j][1] + bb.y, 0.f);
            float v2 = fmaxf(d[i][j][2] + bb.x, 0.f);
            float v3 = fmaxf(d[i][j][3] + bb.y, 0.f);
            *(__half2*)&sm[OFF_U + row*LDU + col]     = __floats2half2_rn(v0, v1);
            *(__half2*)&sm[OFF_U + (row+8)*LDU + col] = __floats2half2_rn(v2, v3);
        }
    }
    __syncthreads();

    // ---------------- phase 2: U(smem) @ W2 -> Co(gmem), act2, N2=256 --------
    #define LOAD_P2(st, kc, pp) do {                                                 \
        int _k0 = (kc) * 64;                                                         \
        _Pragma("unroll")                                                            \
        for (int t = 0; t < 4; t++) {                                                \
            int idx = tid + t*256;                                                   \
            int r = idx >> 4, c8 = (idx & 15) * 8;                                   \
            CPA(sBu + ((st)*SB_H + r*LDB_S + c8)*2,                                  \
                W2 + (size_t)(_k0+r)*256 + (pp)*128 + c8);                           \
        }                                                                            \
        CPC();                                                                       \
    } while (0)

    for (int p = 0; p < 2; p++) {
        #pragma unroll
        for (int i = 0; i < 4; i++)
            #pragma unroll
            for (int j = 0; j < 4; j++)
                #pragma unroll
                for (int e = 0; e < 4; e++) d[i][j][e] = 0.0f;

        LOAD_P2(0, 0, p);
        for (int k = 0; k < 2; k++) {
            if (k == 0) {
                LOAD_P2(1, 1, p);
                asm volatile("cp.async.wait_group 1;" ::: "memory");
            } else {
                asm volatile("cp.async.wait_group 0;" ::: "memory");
            }
            __syncthreads();
            const uint32_t bS = bBase + (k * SB_H) * 2;
            uint32_t bq[2][2][4];
            #pragma unroll
            for (int jj = 0; jj < 2; jj++)
                ldmB4(bq[0][jj], bS + (jj*16) * 2);
            #pragma unroll
            for (int kk = 0; kk < 4; kk++) {
                if (kk < 3) {
                    #pragma unroll
                    for (int jj = 0; jj < 2; jj++)
                        ldmB4(bq[(kk+1)&1][jj], bS + ((kk+1)*16*LDB_S + jj*16) * 2);
                }
                uint32_t af[4][4];
                #pragma unroll
                for (int i = 0; i < 4; i++)
                    ldmA(af[i], aUBase + (i*16*LDU + k*64 + kk*16) * 2);
                #pragma unroll
                for (int i = 0; i < 4; i++)
                    #pragma unroll
                    for (int jj = 0; jj < 2; jj++) {
                        mma16816(d[i][jj*2  ], af[i], bq[kk&1][jj][0], bq[kk&1][jj][1]);
                        mma16816(d[i][jj*2+1], af[i], bq[kk&1][jj][2], bq[kk&1][jj][3]);
                    }
            }
            __syncthreads();
        }

        #pragma unroll
        for (int i = 0; i < 4; i++) {
            int row = m0 + mw + i*16 + (lane >> 2);
            #pragma unroll
            for (int j = 0; j < 4; j++) {
                int gcol = p*128 + nw + j*8 + (lane & 3)*2;
                float2 bb = *(const float2*)&b2p[gcol];
                float v0 = d[i][j][0] + bb.x, v1 = d[i][j][1] + bb.y;
                float v2 = d[i][j][2] + bb.x, v3 = d[i][j][3] + bb.y;
                if (act2 == 1) {
                    v0 = fmaxf(v0,0.f); v1 = fmaxf(v1,0.f);
                    v2 = fmaxf(v2,0.f); v3 = fmaxf(v3,0.f);
                } else if (act2 == 2) {
                    v0 = 1.f/(1.f+__expf(-v0)); v1 = 1.f/(1.f+__expf(-v1));
                    v2 = 1.f/(1.f+__expf(-v2)); v3 = 1.f/(1.f+__expf(-v3));
                }
                *(__half2*)&Co[(size_t)row*256 + gcol]     = __floats2half2_rn(v0, v1);
                *(__half2*)&Co[(size_t)(row+8)*256 + gcol] = __floats2half2_rn(v2, v3);
            }
        }
    }
}

// block (128,8): 8 subgroups of 32 tokens each; fixed-order tree combine.
// Also resets g_cnt for the next graph replay (deterministic).
__global__ void __launch_bounds__(1024) reduce_k(float* __restrict__ out)
{
    __shared__ float2 part[8][128];
    const int b = blockIdx.x, tx = threadIdx.x, ty = threadIdx.y;
    const int* __restrict__ sl = g_slot + b*NTOK + ty*32;
    float2 acc = make_float2(0.f, 0.f);
    #pragma unroll 4
    for (int t = 0; t < 32; t++) {
        int s = sl[t];
        if (s >= 0) {
            float2 fg = __half22float2(*(const __half2*)&g_G [(size_t)s*256 + 2*tx]);
            float2 fv = __half22float2(*(const __half2*)&g_Cv[(size_t)s*256 + 2*tx]);
            acc.x += fg.x * fv.x;
            acc.y += fg.y * fv.y;
        }
    }
    part[ty][tx] = acc;
    __syncthreads();
    if (ty == 0) {
        float2 r = part[0][tx];
        #pragma unroll
        for (int g = 1; g < 8; g++) { r.x += part[g][tx].x; r.y += part[g][tx].y; }
        *(float2*)&out[b*256 + 2*tx] = r;
        if (b == 0 && tx == 0) g_cnt = 0;   // reset for next replay
    }
}

extern "C" void kernel_launch(void* const* d_in, const int* in_sizes, int n_in,
                              void* d_out, int out_size)
{
    const float* h0 = (const float*)d_in[0];
    const float* hT = (const float*)d_in[1];
    const float* W[8]  = { (const float*)d_in[2],  (const float*)d_in[4],
                           (const float*)d_in[6],  (const float*)d_in[8],
                           (const float*)d_in[10], (const float*)d_in[12],
                           (const float*)d_in[14], (const float*)d_in[16] };
    const float* bs[8] = { (const float*)d_in[3],  (const float*)d_in[5],
                           (const float*)d_in[7],  (const float*)d_in[9],
                           (const float*)d_in[11], (const float*)d_in[13],
                           (const float*)d_in[15], (const float*)d_in[17] };
    float* out = (float*)d_out;

    stage1<<<MTOT/32, 1024>>>(h0, hT, W[0],W[1],W[2],W[3],W[4],W[5],W[6],W[7]);

    cudaFuncSetAttribute(fused2_k, cudaFuncAttributeMaxDynamicSharedMemorySize, SMEMB);

    // launch 1: gate L0+L1 (X -> Cg), value L0+L1 (X.hT -> Cv)
    fused2_k<<<dim3(NTILE,1,2), 256, SMEMB>>>(
        0,   0, 512, 512,      0, bs[0],  65536, bs[1], 1, 1,
        0, 256, 512, 256, 163840, bs[4], 196608, bs[5], 1, 2);
    // launch 2: gate L2+L3 (Cg -> G, sigmoid), value L2+L3 (Cv -> Cv, linear)
    fused2_k<<<dim3(NTILE,1,2), 256, SMEMB>>>(
        1, 0, 256, 256,  98304, bs[2], 131072, bs[3], 2, 3,
        2, 0, 256, 256, 229376, bs[6], 262144, bs[7], 0, 2);

    reduce_k<<<BATCH, dim3(128,8)>>>(out);
}